// round 13
// baseline (speedup 1.0000x reference)
#include <cuda_runtime.h>
#include <cstdint>

// ---------------------------------------------------------------------------
// NittaConv2d: 3x3 conv, stride 1, pad 1, N=32 Cin=128 H=W=112 Cout=256, fp32.
// tcgen05 is NOT emittable (harness PTX target is plain sm_103), so this uses
// the sm_80+ baseline tensor path: mma.sync.m16n8k8 tf32 implicit GEMM.
//   D[M=128 spatial, N=256 Cout] += A[m,k] * B[k,n],  K = Cin*9 = 1152
// CTA tile 128x256, BK=32 double-buffered; 8 warps of 64x64.
// A: predicated LDG im2col -> cvt.rna.tf32 -> fragment-packed smem (LDS.128).
// B: weights pre-rounded to tf32 in a scratch __device__ array, cp.async.cg
//    into smem with 36-float row stride (conflict-free consumer LDS).
// ---------------------------------------------------------------------------

#define CIN    128
#define COUT   256
#define HH     112
#define WW     112
#define HW     12544
#define KTOT   1152
#define BK     32
#define NCHUNK 36
#define BM     128
#define GRID   3136          // 32*12544 / 128  (12544 % 128 == 0)

#define BSTRIDE 36           // floats per B smem row (bank spread: (4n+k)&31)

// smem byte offsets
#define SM_BIAS  0
#define SM_A0    1024                 // 128*32*4 = 16384 per buffer
#define SM_A1    (SM_A0 + 16384)
#define SM_B0    (SM_A1 + 16384)      // 256*36*4 = 36864 per buffer
#define SM_B1    (SM_B0 + 36864)
#define SM_TOTAL (SM_B1 + 36864)      // 107520 bytes

// tf32-rounded weights scratch (allocation-free rule: __device__ global)
__device__ float g_wtf32[COUT * KTOT];

static __device__ __forceinline__ uint32_t smem_u32(const void* p) {
    uint32_t a;
    asm("{ .reg .u64 t; cvta.to.shared.u64 t, %1; cvt.u32.u64 %0, t; }"
        : "=r"(a) : "l"(p));
    return a;
}

static __device__ __forceinline__ uint32_t f2tf32(float v) {
    uint32_t u;
    asm("cvt.rna.tf32.f32 %0, %1;" : "=r"(u) : "f"(v));
    return u;
}

__global__ void convert_weights_kernel(const float* __restrict__ wgt) {
    int i = blockIdx.x * blockDim.x + threadIdx.x;
    if (i < COUT * KTOT)
        g_wtf32[i] = __uint_as_float(f2tf32(wgt[i]));
}

// ---- A producer: gather 16 im2col elements for (pos, half) into regs ----
static __device__ __forceinline__ void ldgA(int kc, const float* __restrict__ imgn,
                                            int h, int w, int half, float va[16]) {
    #pragma unroll
    for (int j = 0; j < 16; j++) {
        const int kl = half * 16 + j;
        const int k  = kc * BK + kl;
        const int c  = k / 9;
        const int r  = k - c * 9;
        const int fh = r / 3;
        const int fw = r - fh * 3;
        const int ih = h + fh - 1;
        const int iw = w + fw - 1;
        const bool ok = ((unsigned)ih < (unsigned)HH) && ((unsigned)iw < (unsigned)WW);
        va[j] = ok ? __ldg(imgn + c * HW + ih * WW + iw) : 0.0f;
    }
}

// ---- A producer: round + scatter into fragment-packed layout ----
// element (m=pos, kl): block = (kl/8)*8 + m/16; within block (16x8 tf32, 512B):
//   lane16 = (m%8)*4 + (kl%4), reg = (m%16)/8 + 2*((kl%8)/4)
//   swizzled lane s = (lane16 + mtile) & 31  (consumer applies same rotation)
static __device__ __forceinline__ void stsA(char* abuf, int half, int mtile,
                                            int laneA, int regA, const float va[16]) {
    #pragma unroll
    for (int j = 0; j < 16; j++) {
        const int kl    = half * 16 + j;
        const int kstep = kl >> 3;
        const int cc    = kl & 7;
        const int s     = (laneA + (cc & 3) + mtile) & 31;
        const int off   = ((kstep * 8 + mtile) << 9) + (s << 4)
                        + ((regA + 2 * (cc >> 2)) << 2);
        *(uint32_t*)(abuf + off) = f2tf32(va[j]);
    }
}

// ---- B producer: 8 x 16B cp.async, coalesced (8 threads cover one co row) ----
static __device__ __forceinline__ void cpB(char* bbuf, int kc, int co0, int jb) {
    #pragma unroll
    for (int it = 0; it < 8; it++) {
        const int co = co0 + 32 * it;
        const float* src = g_wtf32 + (size_t)co * KTOT + kc * BK + jb * 4;
        const uint32_t dst = smem_u32(bbuf + (co * BSTRIDE + jb * 4) * 4);
        asm volatile("cp.async.cg.shared.global [%0], [%1], 16;"
                     :: "r"(dst), "l"(src) : "memory");
    }
}

// ---- consumer: 4 ksteps x (4 A frags, 8 B frags, 32 mmas) ----
static __device__ __forceinline__ void compute_chunk(const char* abuf, const char* bbuf,
                                                     int mw, int nw, int lane,
                                                     float acc[4][8][4]) {
    #pragma unroll
    for (int ks = 0; ks < 4; ks++) {
        uint32_t a[4][4];
        #pragma unroll
        for (int mi = 0; mi < 4; mi++) {
            const int mt = mw * 4 + mi;
            const int s  = (lane + mt) & 31;
            const uint4 v = *(const uint4*)(abuf + ((ks * 8 + mt) << 9) + (s << 4));
            a[mi][0] = v.x; a[mi][1] = v.y; a[mi][2] = v.z; a[mi][3] = v.w;
        }
        uint32_t b[8][2];
        const int k0 = ks * 8 + (lane & 3);
        #pragma unroll
        for (int ni = 0; ni < 8; ni++) {
            const int nn = nw * 64 + ni * 8 + (lane >> 2);
            b[ni][0] = *(const uint32_t*)(bbuf + (nn * BSTRIDE + k0) * 4);
            b[ni][1] = *(const uint32_t*)(bbuf + (nn * BSTRIDE + k0 + 4) * 4);
        }
        #pragma unroll
        for (int mi = 0; mi < 4; mi++) {
            #pragma unroll
            for (int ni = 0; ni < 8; ni++) {
                asm volatile(
                    "mma.sync.aligned.m16n8k8.row.col.f32.tf32.tf32.f32 "
                    "{%0,%1,%2,%3}, {%4,%5,%6,%7}, {%8,%9}, {%0,%1,%2,%3};"
                    : "+f"(acc[mi][ni][0]), "+f"(acc[mi][ni][1]),
                      "+f"(acc[mi][ni][2]), "+f"(acc[mi][ni][3])
                    : "r"(a[mi][0]), "r"(a[mi][1]), "r"(a[mi][2]), "r"(a[mi][3]),
                      "r"(b[ni][0]), "r"(b[ni][1]));
            }
        }
    }
}

__global__ void __launch_bounds__(256, 1)
nitta_conv_mma_kernel(float* __restrict__ out,
                      const float* __restrict__ img,
                      const float* __restrict__ bias)
{
    extern __shared__ char smem[];
    const int tid  = threadIdx.x;
    const int wid  = tid >> 5;
    const int lane = tid & 31;

    float* biasS = (float*)(smem + SM_BIAS);
    biasS[tid] = bias[tid];          // 256 threads, 256 values

    // ---- producer coords ----
    const int pos  = tid & 127;      // A row (spatial within tile)
    const int half = tid >> 7;       // which 16 of the 32 k's
    const int p0   = blockIdx.x * BM;
    const int n    = p0 / HW;
    const int hw0  = p0 - n * HW;
    const int hw   = hw0 + pos;
    const int h    = hw / WW;
    const int w    = hw - h * WW;
    const float* __restrict__ imgn = img + (size_t)n * (CIN * HW);

    const int mtile = pos >> 4;
    const int rr    = pos & 15;
    const int laneA = (rr & 7) * 4;
    const int regA  = rr >> 3;

    const int jb  = tid & 7;         // B: 16B column
    const int co0 = tid >> 3;        // B: base co row (0..31)

    // ---- consumer coords: warp (mw, nw) owns 64x64 ----
    const int nw = wid & 3;
    const int mw = wid >> 2;

    float acc[4][8][4];
    #pragma unroll
    for (int i = 0; i < 4; i++)
        #pragma unroll
        for (int j = 0; j < 8; j++)
            #pragma unroll
            for (int q = 0; q < 4; q++) acc[i][j][q] = 0.0f;

    // ---- prologue: fill buffer 0 with chunk 0 ----
    float va[16];
    cpB(smem + SM_B0, 0, co0, jb);
    asm volatile("cp.async.commit_group;" ::: "memory");
    ldgA(0, imgn, h, w, half, va);
    stsA(smem + SM_A0, half, mtile, laneA, regA, va);
    asm volatile("cp.async.wait_group 0;" ::: "memory");
    __syncthreads();

    // ---- main loop: compute chunk kc, prefetch kc+1 ----
    for (int kc = 0; kc < NCHUNK; kc++) {
        char* ab  = (kc & 1) ? (smem + SM_A1) : (smem + SM_A0);
        char* bb  = (kc & 1) ? (smem + SM_B1) : (smem + SM_B0);
        char* abN = (kc & 1) ? (smem + SM_A0) : (smem + SM_A1);
        char* bbN = (kc & 1) ? (smem + SM_B0) : (smem + SM_B1);
        const bool more = (kc + 1 < NCHUNK);

        if (more) {
            cpB(bbN, kc + 1, co0, jb);
            asm volatile("cp.async.commit_group;" ::: "memory");
            ldgA(kc + 1, imgn, h, w, half, va);   // latency overlapped by mmas
        }

        compute_chunk(ab, bb, mw, nw, lane, acc);

        if (more) {
            stsA(abN, half, mtile, laneA, regA, va);
            asm volatile("cp.async.wait_group 0;" ::: "memory");
        }
        __syncthreads();
    }

    // ---- epilogue: D frag (d0: r,2t | d1: r,2t+1 | d2: r+8,2t | d3: r+8,2t+1) ----
    {
        const int rowb = mw * 64 + (lane >> 2);
        const int t2   = (lane & 3) * 2;
        float* __restrict__ outn = out + (size_t)n * ((size_t)COUT * HW) + hw0;
        #pragma unroll
        for (int mi = 0; mi < 4; mi++) {
            const int r0 = rowb + mi * 16;
            #pragma unroll
            for (int ni = 0; ni < 8; ni++) {
                const int co = nw * 64 + ni * 8 + t2;
                const float b0 = biasS[co];
                const float b1 = biasS[co + 1];
                outn[(size_t)co * HW + r0]           = acc[mi][ni][0] + b0;
                outn[(size_t)(co + 1) * HW + r0]     = acc[mi][ni][1] + b1;
                outn[(size_t)co * HW + r0 + 8]       = acc[mi][ni][2] + b0;
                outn[(size_t)(co + 1) * HW + r0 + 8] = acc[mi][ni][3] + b1;
            }
        }
    }
}

extern "C" void kernel_launch(void* const* d_in, const int* in_sizes, int n_in,
                              void* d_out, int out_size)
{
    const float* img  = (const float*)d_in[0];   // 32*128*112*112
    const float* wgt  = (const float*)d_in[1];   // 256*128*3*3
    const float* bias = (const float*)d_in[2];   // 256
    float* out = (float*)d_out;                  // 32*256*112*112

    convert_weights_kernel<<<(COUT * KTOT + 255) / 256, 256>>>(wgt);

    cudaFuncSetAttribute(nitta_conv_mma_kernel,
                         cudaFuncAttributeMaxDynamicSharedMemorySize, SM_TOTAL);
    nitta_conv_mma_kernel<<<GRID, 256, SM_TOTAL>>>(out, img, bias);
}

// round 14
// speedup vs baseline: 1.5483x; 1.5483x over previous
#include <cuda_runtime.h>
#include <cuda_fp16.h>
#include <cstdint>

// ---------------------------------------------------------------------------
// NittaConv2d: 3x3 conv, stride 1, pad 1, N=32 Cin=128 H=W=112 Cout=256, fp32.
// fp16 implicit GEMM on mma.sync.m16n8k16 (tcgen05 not emittable: harness
// compiles PTX for plain sm_103).
//   D[128 pos x 256 co] += A[pos,k] * B[k,co],  K reordered: k = r*128 + c
// so each BK=32 chunk has a FIXED filter tap r -> trivial im2col addressing.
// 512 threads, 16 warps of 64x32; double-buffered smem; A via predicated LDG
// -> half2 STS fragment-packed (one LDS.128/frag); B via cp.async from a
// pre-permuted/pre-converted half scratch array (stride-40 rows, conflict-free).
// ---------------------------------------------------------------------------

#define CIN    128
#define COUT   256
#define HH     112
#define WW     112
#define HW     12544
#define KTOT   1152
#define BK     32
#define NCHUNK 36
#define BM     128
#define GRID   3136          // 32*12544/128
#define THREADS 512

// smem byte offsets
#define SM_BIAS  0                    // 256 floats = 1024 B
#define SM_A0    1024                 // 16 frag-blocks * 512B = 8192 per buffer
#define SM_A1    9216
#define SM_B0    17408                // 256 rows * 80B = 20480 per buffer
#define SM_B1    37888
#define SM_TOTAL 58368

#define BROW     80                   // B smem row stride bytes (40 halves)

// pre-permuted (k = r*128+c), pre-converted weights
__device__ __half g_wh[COUT * KTOT];

static __device__ __forceinline__ uint32_t smem_u32(const void* p) {
    uint32_t a;
    asm("{ .reg .u64 t; cvta.to.shared.u64 t, %1; cvt.u32.u64 %0, t; }"
        : "=r"(a) : "l"(p));
    return a;
}

__global__ void convert_weights_kernel(const float* __restrict__ wgt) {
    int i = blockIdx.x * blockDim.x + threadIdx.x;   // output index (coalesced write)
    if (i < COUT * KTOT) {
        const int co = i / KTOT;
        const int ko = i - co * KTOT;                // r*128 + c
        const int r  = ko >> 7;
        const int c  = ko & 127;
        g_wh[i] = __float2half(wgt[co * KTOT + c * 9 + r]);
    }
}

// ---- A producer: 8 LDGs, fixed tap r per chunk, stride HW along c ----
static __device__ __forceinline__ void ldgA(int kc, const float* __restrict__ aptr,
                                            unsigned okm, int kq, float va[8]) {
    const int r    = kc >> 2;                 // fixed filter tap for this chunk
    const int fh   = r / 3;
    const int roff = (fh - 1) * WW + (r - fh * 3 - 1);
    const bool ok  = (okm >> r) & 1u;
    const float* s = aptr + roff + (size_t)((kc & 3) * 32 + kq * 8) * HW;
    #pragma unroll
    for (int j = 0; j < 8; j++)
        va[j] = ok ? __ldg(s + (size_t)j * HW) : 0.0f;
}

// ---- A producer: convert to half2, scatter fragment-packed ----
static __device__ __forceinline__ void stsA(char* abuf, int stsBase, const float va[8]) {
    #pragma unroll
    for (int j = 0; j < 8; j += 2) {
        const __half2 h = __floats2half2_rn(va[j], va[j + 1]);
        *(uint32_t*)(abuf + stsBase + (j >> 1) * 16) =
            *(const uint32_t*)&h;
    }
}

// ---- B producer: 2 x 16B cp.async per thread (256 rows x 64B per chunk) ----
static __device__ __forceinline__ void cpB(char* bbuf, int kc, int coB, int jb) {
    #pragma unroll
    for (int it = 0; it < 2; it++) {
        const int co = coB + 128 * it;
        const __half* src = g_wh + (size_t)co * KTOT + kc * BK + jb * 8;
        const uint32_t dst = smem_u32(bbuf + co * BROW + jb * 16);
        asm volatile("cp.async.cg.shared.global [%0], [%1], 16;"
                     :: "r"(dst), "l"(src) : "memory");
    }
}

// ---- consumer: 2 ksteps (k16) x (4 A frags, 4 B frags, 16 mmas) ----
static __device__ __forceinline__ void compute_chunk(const char* abuf, const char* bbuf,
                                                     int mw, int nw, int lane,
                                                     float acc[4][4][4]) {
    #pragma unroll
    for (int ks = 0; ks < 2; ks++) {
        uint32_t a[4][4];
        #pragma unroll
        for (int mi = 0; mi < 4; mi++) {
            const uint4 v = *(const uint4*)(abuf + ((ks * 8 + mw * 4 + mi) << 9)
                                            + (lane << 4));
            a[mi][0] = v.x; a[mi][1] = v.y; a[mi][2] = v.z; a[mi][3] = v.w;
        }
        uint32_t b[4][2];
        #pragma unroll
        for (int ni = 0; ni < 4; ni++) {
            const int co = nw * 32 + ni * 8 + (lane >> 2);
            const char* p = bbuf + co * BROW + ks * 32 + (lane & 3) * 4;
            b[ni][0] = *(const uint32_t*)p;
            b[ni][1] = *(const uint32_t*)(p + 16);
        }
        #pragma unroll
        for (int mi = 0; mi < 4; mi++) {
            #pragma unroll
            for (int ni = 0; ni < 4; ni++) {
                asm volatile(
                    "mma.sync.aligned.m16n8k16.row.col.f32.f16.f16.f32 "
                    "{%0,%1,%2,%3}, {%4,%5,%6,%7}, {%8,%9}, {%0,%1,%2,%3};"
                    : "+f"(acc[mi][ni][0]), "+f"(acc[mi][ni][1]),
                      "+f"(acc[mi][ni][2]), "+f"(acc[mi][ni][3])
                    : "r"(a[mi][0]), "r"(a[mi][1]), "r"(a[mi][2]), "r"(a[mi][3]),
                      "r"(b[ni][0]), "r"(b[ni][1]));
            }
        }
    }
}

__global__ void __launch_bounds__(THREADS, 1)
nitta_conv_fp16_kernel(float* __restrict__ out,
                       const float* __restrict__ img,
                       const float* __restrict__ bias)
{
    extern __shared__ char smem[];
    const int tid  = threadIdx.x;
    const int wid  = tid >> 5;
    const int lane = tid & 31;

    float* biasS = (float*)(smem + SM_BIAS);
    if (tid < COUT) biasS[tid] = bias[tid];

    // ---- producer coords ----
    const int pos = tid & 127;       // spatial row within tile
    const int kq  = tid >> 7;        // 0..3: which 8 k's of the 32-chunk
    const int p0  = blockIdx.x * BM;
    const int n   = p0 / HW;
    const int hw0 = p0 - n * HW;
    const int hw  = hw0 + pos;
    const int h   = hw / WW;
    const int w   = hw - h * WW;
    const float* __restrict__ aptr = img + (size_t)n * (CIN * HW) + hw;

    // 9-bit in-bounds mask per thread (tap r -> valid?)
    unsigned okm = 0;
    #pragma unroll
    for (int r = 0; r < 9; r++) {
        const int fh = r / 3, fw = r - fh * 3;
        const int ih = h + fh - 1, iw = w + fw - 1;
        if (((unsigned)ih < (unsigned)HH) && ((unsigned)iw < (unsigned)WW))
            okm |= 1u << r;
    }

    // A STS base: frag block (ks*8 + mtile), lane (rw&7)*4 + j/2, slot (rw>>3)+2*khi
    const int mtile = pos >> 4;
    const int rw    = pos & 15;
    const int ks    = kq >> 1;
    const int khi   = kq & 1;
    const int stsBase = ((ks * 8 + mtile) << 9) + ((rw & 7) << 6)
                      + ((rw >> 3) << 2) + (khi << 3);

    const int jb  = tid & 3;         // B: 16B column (4 per row)
    const int coB = tid >> 2;        // B: row 0..127 (+128 on 2nd pass)

    // ---- consumer coords: 16 warps, warp (mw, nw) owns 64x32 ----
    const int mw = wid >> 3;         // 0..1
    const int nw = wid & 7;          // 0..7

    float acc[4][4][4];
    #pragma unroll
    for (int i = 0; i < 4; i++)
        #pragma unroll
        for (int j = 0; j < 4; j++)
            #pragma unroll
            for (int q = 0; q < 4; q++) acc[i][j][q] = 0.0f;

    // ---- prologue: fill buffer 0 with chunk 0 ----
    float va[8];
    cpB(smem + SM_B0, 0, coB, jb);
    asm volatile("cp.async.commit_group;" ::: "memory");
    ldgA(0, aptr, okm, kq, va);
    stsA(smem + SM_A0, stsBase, va);
    asm volatile("cp.async.wait_group 0;" ::: "memory");
    __syncthreads();

    // ---- main loop: compute kc, prefetch kc+1 ----
    for (int kc = 0; kc < NCHUNK; kc++) {
        char* ab  = (kc & 1) ? (smem + SM_A1) : (smem + SM_A0);
        char* bb  = (kc & 1) ? (smem + SM_B1) : (smem + SM_B0);
        char* abN = (kc & 1) ? (smem + SM_A0) : (smem + SM_A1);
        char* bbN = (kc & 1) ? (smem + SM_B0) : (smem + SM_B1);
        const bool more = (kc + 1 < NCHUNK);

        if (more) {
            cpB(bbN, kc + 1, coB, jb);
            asm volatile("cp.async.commit_group;" ::: "memory");
            ldgA(kc + 1, aptr, okm, kq, va);   // LDG latency hidden by mmas
        }

        compute_chunk(ab, bb, mw, nw, lane, acc);

        if (more) {
            stsA(abN, stsBase, va);
            asm volatile("cp.async.wait_group 0;" ::: "memory");
        }
        __syncthreads();
    }

    // ---- epilogue: D frag rows = spatial pos, cols = co; + bias; STG.32 ----
    {
        const int rowb = mw * 64 + (lane >> 2);
        const int t2   = (lane & 3) * 2;
        float* __restrict__ outn = out + (size_t)n * ((size_t)COUT * HW) + hw0;
        #pragma unroll
        for (int mi = 0; mi < 4; mi++) {
            const int r0 = rowb + mi * 16;
            #pragma unroll
            for (int ni = 0; ni < 4; ni++) {
                const int co = nw * 32 + ni * 8 + t2;
                const float b0 = biasS[co];
                const float b1 = biasS[co + 1];
                outn[(size_t)co * HW + r0]           = acc[mi][ni][0] + b0;
                outn[(size_t)(co + 1) * HW + r0]     = acc[mi][ni][1] + b1;
                outn[(size_t)co * HW + r0 + 8]       = acc[mi][ni][2] + b0;
                outn[(size_t)(co + 1) * HW + r0 + 8] = acc[mi][ni][3] + b1;
            }
        }
    }
}

extern "C" void kernel_launch(void* const* d_in, const int* in_sizes, int n_in,
                              void* d_out, int out_size)
{
    const float* img  = (const float*)d_in[0];   // 32*128*112*112
    const float* wgt  = (const float*)d_in[1];   // 256*128*3*3
    const float* bias = (const float*)d_in[2];   // 256
    float* out = (float*)d_out;                  // 32*256*112*112

    convert_weights_kernel<<<(COUT * KTOT + 255) / 256, 256>>>(wgt);

    cudaFuncSetAttribute(nitta_conv_fp16_kernel,
                         cudaFuncAttributeMaxDynamicSharedMemorySize, SM_TOTAL);
    nitta_conv_fp16_kernel<<<GRID, THREADS, SM_TOTAL>>>(out, img, bias);
}

// round 15
// speedup vs baseline: 1.8013x; 1.1634x over previous
#include <cuda_runtime.h>
#include <cuda_fp16.h>
#include <cstdint>

// ---------------------------------------------------------------------------
// NittaConv2d: 3x3 conv, stride 1, pad 1, N=32 Cin=128 H=W=112 Cout=256, fp32.
// fp16 implicit GEMM on mma.sync.m16n8k16 (plain sm_103 PTX target).
//   D[128 pos x 256 co] += A[pos,k] * B[k,co],  K reordered: k = r*128 + c
// BK=64 per barrier (one filter tap per iter). 512 threads, 16 warps of 64x32.
// A producer: each thread owns ONE fragment-lane 16B (2 rows x 4 k) ->
//   8 LDG.32 + 1 STS.128, bank-conflict-free both directions.
// B: cp.async from pre-permuted half weights, 144B row stride (conflict-free).
// ---------------------------------------------------------------------------

#define CIN    128
#define COUT   256
#define HH     112
#define WW     112
#define HW     12544
#define KTOT   1152
#define BK     64
#define NITER  18
#define BM     128
#define GRID   3136
#define THREADS 512

// smem byte offsets
#define SM_BIAS  0                    // 1024 B
#define SM_A0    1024                 // 32 frag-blocks * 512B = 16384 / buffer
#define SM_A1    17408
#define SM_B0    33792                // 256 rows * 144B = 36864 / buffer
#define SM_B1    70656
#define SM_TOTAL 107520

#define BROW     144                  // B smem row stride bytes (36 banks)

// pre-permuted (k = r*128+c), pre-converted weights
__device__ __half g_wh[COUT * KTOT];

static __device__ __forceinline__ uint32_t smem_u32(const void* p) {
    uint32_t a;
    asm("{ .reg .u64 t; cvta.to.shared.u64 t, %1; cvt.u32.u64 %0, t; }"
        : "=r"(a) : "l"(p));
    return a;
}

__global__ void convert_weights_kernel(const float* __restrict__ wgt) {
    int i = blockIdx.x * blockDim.x + threadIdx.x;   // coalesced output index
    if (i < COUT * KTOT) {
        const int co = i / KTOT;
        const int ko = i - co * KTOT;                // r*128 + c
        const int r  = ko >> 7;
        const int c  = ko & 127;
        g_wh[i] = __float2half(wgt[co * KTOT + c * 9 + r]);
    }
}

// ---- A producer: thread owns frag-lane (2 rows x {2q,2q+1,2q+8,2q+9}) of
//      two blocks (ks = ksP and ksP+2). 16 LDG.32 total. ----
static __device__ __forceinline__ void ldgA(int iter,
                                            const float* __restrict__ ap0,
                                            const float* __restrict__ ap1,
                                            unsigned m0, unsigned m1,
                                            int ksP, int q, float va[16]) {
    const int r    = iter >> 1;
    const int fh   = r / 3;
    const int roff = (fh - 1) * WW + (r - fh * 3 - 1);
    const bool ok0 = (m0 >> r) & 1u;
    const bool ok1 = (m1 >> r) & 1u;
    const int c0   = (iter & 1) * 64;
    #pragma unroll
    for (int blk = 0; blk < 2; blk++) {
        const int cb = c0 + (ksP + 2 * blk) * 16;
        const float* s0 = ap0 + roff + (size_t)cb * HW;
        const float* s1 = ap1 + roff + (size_t)cb * HW;
        float* v = va + blk * 8;
        const int klo = 2 * q;
        v[0] = ok0 ? __ldg(s0 + (size_t)klo * HW)       : 0.0f;
        v[1] = ok0 ? __ldg(s0 + (size_t)(klo + 1) * HW) : 0.0f;
        v[2] = ok1 ? __ldg(s1 + (size_t)klo * HW)       : 0.0f;
        v[3] = ok1 ? __ldg(s1 + (size_t)(klo + 1) * HW) : 0.0f;
        v[4] = ok0 ? __ldg(s0 + (size_t)(klo + 8) * HW) : 0.0f;
        v[5] = ok0 ? __ldg(s0 + (size_t)(klo + 9) * HW) : 0.0f;
        v[6] = ok1 ? __ldg(s1 + (size_t)(klo + 8) * HW) : 0.0f;
        v[7] = ok1 ? __ldg(s1 + (size_t)(klo + 9) * HW) : 0.0f;
    }
}

// ---- A producer: 2x STS.128, exactly mirroring consumer LDS.128 ----
static __device__ __forceinline__ void stsA(char* abuf, int ksP, int mtileP,
                                            int lane, const float va[16]) {
    #pragma unroll
    for (int blk = 0; blk < 2; blk++) {
        const float* v = va + blk * 8;
        const __half2 h0 = __floats2half2_rn(v[0], v[1]);
        const __half2 h1 = __floats2half2_rn(v[2], v[3]);
        const __half2 h2 = __floats2half2_rn(v[4], v[5]);
        const __half2 h3 = __floats2half2_rn(v[6], v[7]);
        uint4 u;
        u.x = *(const uint32_t*)&h0;
        u.y = *(const uint32_t*)&h1;
        u.z = *(const uint32_t*)&h2;
        u.w = *(const uint32_t*)&h3;
        const int ks = ksP + 2 * blk;
        *(uint4*)(abuf + (((ks * 8 + mtileP) << 9) + (lane << 4))) = u;
    }
}

// ---- B producer: 4 x 16B cp.async (256 rows x 128B per iter) ----
static __device__ __forceinline__ void cpB(char* bbuf, int iter, int coB, int jb) {
    #pragma unroll
    for (int it = 0; it < 4; it++) {
        const int co = coB + 64 * it;
        const __half* src = g_wh + (size_t)co * KTOT + iter * BK + jb * 8;
        const uint32_t dst = smem_u32(bbuf + co * BROW + jb * 16);
        asm volatile("cp.async.cg.shared.global [%0], [%1], 16;"
                     :: "r"(dst), "l"(src) : "memory");
    }
}

// ---- consumer: 2 of the 4 k16 steps ----
static __device__ __forceinline__ void compute_half(const char* abuf, const char* bbuf,
                                                    int mw, int nw, int lane, int ks0,
                                                    float acc[4][4][4]) {
    #pragma unroll
    for (int ks = ks0; ks < ks0 + 2; ks++) {
        uint32_t a[4][4];
        #pragma unroll
        for (int mi = 0; mi < 4; mi++) {
            const uint4 v = *(const uint4*)(abuf + ((ks * 8 + mw * 4 + mi) << 9)
                                            + (lane << 4));
            a[mi][0] = v.x; a[mi][1] = v.y; a[mi][2] = v.z; a[mi][3] = v.w;
        }
        uint32_t b[4][2];
        #pragma unroll
        for (int ni = 0; ni < 4; ni++) {
            const int co = nw * 32 + ni * 8 + (lane >> 2);
            const char* p = bbuf + co * BROW + ks * 32 + (lane & 3) * 4;
            b[ni][0] = *(const uint32_t*)p;
            b[ni][1] = *(const uint32_t*)(p + 16);
        }
        #pragma unroll
        for (int mi = 0; mi < 4; mi++) {
            #pragma unroll
            for (int ni = 0; ni < 4; ni++) {
                asm volatile(
                    "mma.sync.aligned.m16n8k16.row.col.f32.f16.f16.f32 "
                    "{%0,%1,%2,%3}, {%4,%5,%6,%7}, {%8,%9}, {%0,%1,%2,%3};"
                    : "+f"(acc[mi][ni][0]), "+f"(acc[mi][ni][1]),
                      "+f"(acc[mi][ni][2]), "+f"(acc[mi][ni][3])
                    : "r"(a[mi][0]), "r"(a[mi][1]), "r"(a[mi][2]), "r"(a[mi][3]),
                      "r"(b[ni][0]), "r"(b[ni][1]));
            }
        }
    }
}

__global__ void __launch_bounds__(THREADS, 1)
nitta_conv_v3_kernel(float* __restrict__ out,
                     const float* __restrict__ img,
                     const float* __restrict__ bias)
{
    extern __shared__ char smem[];
    const int tid  = threadIdx.x;
    const int wid  = tid >> 5;
    const int lane = tid & 31;

    float* biasS = (float*)(smem + SM_BIAS);
    if (tid < COUT) biasS[tid] = bias[tid];

    const int p0  = blockIdx.x * BM;
    const int n   = p0 / HW;
    const int hw0 = p0 - n * HW;

    // ---- A producer coords: warp wid handles blocks {wid, wid+16} ----
    const int mtileP = wid & 7;
    const int ksP    = wid >> 3;       // 0..1 (second block: +2)
    const int vrow   = lane >> 2;
    const int q      = lane & 3;
    const int pos0   = mtileP * 16 + vrow;      // row r0; r1 = +8
    const int hwA0   = hw0 + pos0;
    const int hwA1   = hwA0 + 8;
    const int h0 = hwA0 / WW, w0 = hwA0 - h0 * WW;
    const int h1 = hwA1 / WW, w1 = hwA1 - h1 * WW;
    const float* __restrict__ imgn = img + (size_t)n * (CIN * HW);
    const float* __restrict__ ap0 = imgn + hwA0;
    const float* __restrict__ ap1 = imgn + hwA1;

    unsigned m0 = 0, m1 = 0;
    #pragma unroll
    for (int r = 0; r < 9; r++) {
        const int fh = r / 3, fw = r - fh * 3;
        if (((unsigned)(h0 + fh - 1) < (unsigned)HH) &&
            ((unsigned)(w0 + fw - 1) < (unsigned)WW)) m0 |= 1u << r;
        if (((unsigned)(h1 + fh - 1) < (unsigned)HH) &&
            ((unsigned)(w1 + fw - 1) < (unsigned)WW)) m1 |= 1u << r;
    }

    // ---- B producer coords ----
    const int jb  = tid & 7;
    const int coB = tid >> 3;          // 0..63 (+64*it)

    // ---- consumer coords: warp (mw, nw) owns 64x32 ----
    const int mw = wid >> 3;
    const int nw = wid & 7;

    float acc[4][4][4];
    #pragma unroll
    for (int i = 0; i < 4; i++)
        #pragma unroll
        for (int j = 0; j < 4; j++)
            #pragma unroll
            for (int s = 0; s < 4; s++) acc[i][j][s] = 0.0f;

    // ---- prologue: fill buffer 0 with iter 0 ----
    float va[16];
    cpB(smem + SM_B0, 0, coB, jb);
    asm volatile("cp.async.commit_group;" ::: "memory");
    ldgA(0, ap0, ap1, m0, m1, ksP, q, va);
    stsA(smem + SM_A0, ksP, mtileP, lane, va);
    asm volatile("cp.async.wait_group 0;" ::: "memory");
    __syncthreads();

    // ---- main loop ----
    for (int i = 0; i < NITER; i++) {
        char* ab  = (i & 1) ? (smem + SM_A1) : (smem + SM_A0);
        char* bb  = (i & 1) ? (smem + SM_B1) : (smem + SM_B0);
        char* abN = (i & 1) ? (smem + SM_A0) : (smem + SM_A1);
        char* bbN = (i & 1) ? (smem + SM_B0) : (smem + SM_B1);
        const bool more = (i + 1 < NITER);

        if (more) {
            cpB(bbN, i + 1, coB, jb);
            asm volatile("cp.async.commit_group;" ::: "memory");
            ldgA(i + 1, ap0, ap1, m0, m1, ksP, q, va);
        }

        compute_half(ab, bb, mw, nw, lane, 0, acc);   // ks 0,1 (hides LDG lat)

        if (more) stsA(abN, ksP, mtileP, lane, va);

        compute_half(ab, bb, mw, nw, lane, 2, acc);   // ks 2,3

        if (more) asm volatile("cp.async.wait_group 0;" ::: "memory");
        __syncthreads();
    }

    // ---- epilogue ----
    {
        const int rowb = mw * 64 + (lane >> 2);
        const int t2   = (lane & 3) * 2;
        float* __restrict__ outn = out + (size_t)n * ((size_t)COUT * HW) + hw0;
        #pragma unroll
        for (int mi = 0; mi < 4; mi++) {
            const int r0 = rowb + mi * 16;
            #pragma unroll
            for (int ni = 0; ni < 4; ni++) {
                const int co = nw * 32 + ni * 8 + t2;
                const float b0 = biasS[co];
                const float b1 = biasS[co + 1];
                outn[(size_t)co * HW + r0]           = acc[mi][ni][0] + b0;
                outn[(size_t)(co + 1) * HW + r0]     = acc[mi][ni][1] + b1;
                outn[(size_t)co * HW + r0 + 8]       = acc[mi][ni][2] + b0;
                outn[(size_t)(co + 1) * HW + r0 + 8] = acc[mi][ni][3] + b1;
            }
        }
    }
}

extern "C" void kernel_launch(void* const* d_in, const int* in_sizes, int n_in,
                              void* d_out, int out_size)
{
    const float* img  = (const float*)d_in[0];   // 32*128*112*112
    const float* wgt  = (const float*)d_in[1];   // 256*128*3*3
    const float* bias = (const float*)d_in[2];   // 256
    float* out = (float*)d_out;                  // 32*256*112*112

    convert_weights_kernel<<<(COUT * KTOT + 255) / 256, 256>>>(wgt);

    cudaFuncSetAttribute(nitta_conv_v3_kernel,
                         cudaFuncAttributeMaxDynamicSharedMemorySize, SM_TOTAL);
    nitta_conv_v3_kernel<<<GRID, THREADS, SM_TOTAL>>>(out, img, bias);
}